// round 3
// baseline (speedup 1.0000x reference)
#include <cuda_runtime.h>
#include <math.h>

#define MPTS 8192
#define KNN  16
#define CINF 128
#define MK   (MPTS*KNN)   // 131072

// ---------------- scratch (device globals; no allocation allowed) ----------------
__device__ float4 g_pos4[MPTS];      // xyz + d2 in .w
__device__ int    g_idx[MK];
__device__ float  g_A1[32*MK];       // mlp1 layer1 (pre-BN), channel-major [32][131072]
__device__ float  g_A2[32*MK];       // mlp1 layer2 (pre-BN)
__device__ float  g_T0[256*MPTS];    // mlp2 dense   (pre-BN), channel-major [256][8192]
__device__ float  g_T1[256*MPTS];    // gconv-a      (pre-BN)
__device__ float  g_T2[256*MPTS];    // gconv-b      (pre-BN)
__device__ float  g_Y[MPTS*320];     // depthwise output, row-major [8192][320]
__device__ float  g_stats[2048];     // BN scale/shift packs

#define OFF_S1 0      // 32 scale + 32 shift
#define OFF_S2 64
#define OFF_SA 128    // 256 + 256
#define OFF_SB 640
#define OFF_SC 1152

__device__ __forceinline__ float elu_f(float x){ return x > 0.f ? x : expm1f(x); }

// ---------------- pack pos into float4, with d2 = (x*x + y*y) + z*z in .w ----------------
__global__ void pack_pos_kernel(const float* __restrict__ pos){
    int i = blockIdx.x*blockDim.x + threadIdx.x;
    if (i < MPTS){
        float x = pos[3*i], y = pos[3*i+1], z = pos[3*i+2];
        float d2 = __fadd_rn(__fadd_rn(__fmul_rn(x,x), __fmul_rn(y,y)), __fmul_rn(z,z));
        g_pos4[i] = make_float4(x, y, z, d2);
    }
}

// ---------------- exact kNN replicating reference's Gram-form distance ----------------
// dot replicates cuBLAS SGEMM K=3 ascending fma chain: fma(a2,b2, fma(a1,b1, rn(a0*b0)));
// dist = (d2_q + d2_j) - 2*dot, matching XLA's fused elementwise (add, then sub of 2*gemm).
__global__ void __launch_bounds__(128) knn_kernel(){
    int lane  = threadIdx.x & 31;
    int split = threadIdx.x >> 5;
    int q = blockIdx.x*32 + lane;
    float4 qp = g_pos4[q];

    float best[16]; int bidx[16];
    #pragma unroll
    for (int s = 0; s < 16; s++){ best[s] = 3.4e38f; bidx[s] = 0x7fffffff; }

    int j0 = split*2048;
    #pragma unroll 4
    for (int j = j0; j < j0 + 2048; j++){
        float4 c = g_pos4[j];
        float dot = __fmaf_rn(qp.z, c.z,
                    __fmaf_rn(qp.y, c.y,
                    __fmul_rn(qp.x, c.x)));
        float d = __fsub_rn(__fadd_rn(qp.w, c.w), __fmul_rn(2.0f, dot));
        if (d < best[15]) {                       // strict '<': ascending-j scan keeps lowest-index-first ties
            float cd = d; int cj = j;
            #pragma unroll
            for (int s = 0; s < 16; s++){
                if (cd < best[s]) {
                    float td = best[s]; best[s] = cd; cd = td;
                    int   ti = bidx[s]; bidx[s] = cj; cj = ti;
                }
            }
        }
    }

    __shared__ float sd[4][32][16];
    __shared__ int   si[4][32][16];
    #pragma unroll
    for (int s = 0; s < 16; s++){ sd[split][lane][s] = best[s]; si[split][lane][s] = bidx[s]; }
    __syncthreads();

    if (split == 0){
        // tie-aware merge of the other 3 sorted lists (key = (dist, idx), idx ascending on ties)
        #pragma unroll
        for (int sp = 1; sp < 4; sp++){
            #pragma unroll
            for (int e = 0; e < 16; e++){
                float d = sd[sp][lane][e]; int j = si[sp][lane][e];
                bool ins = (d < best[15]) || (d == best[15] && j < bidx[15]);
                if (ins){
                    float cd = d; int cj = j;
                    #pragma unroll
                    for (int s = 0; s < 16; s++){
                        bool lt = (cd < best[s]) || (cd == best[s] && cj < bidx[s]);
                        if (lt){
                            float td = best[s]; best[s] = cd; cd = td;
                            int   ti = bidx[s]; bidx[s] = cj; cj = ti;
                        }
                    }
                }
            }
        }
        #pragma unroll
        for (int e = 0; e < 16; e++) g_idx[q*16 + e] = bidx[e];
    }
}

// ---------------- mlp1 layer 1: rel(3) -> 32, elu (pre-BN stored) ----------------
__global__ void __launch_bounds__(256) mlp1a_kernel(const float* __restrict__ w1a,
                                                    const float* __restrict__ b1a){
    __shared__ float w[96], b[32];
    int t = threadIdx.x;
    if (t < 96) w[t] = w1a[t];
    if (t < 32) b[t] = b1a[t];
    __syncthreads();
    int r = blockIdx.x*256 + t;          // 0..131071
    int m = r >> 4;
    int nb = g_idx[r];
    float4 pm = g_pos4[m], pn = g_pos4[nb];
    float rx = pn.x - pm.x, ry = pn.y - pm.y, rz = pn.z - pm.z;
    #pragma unroll
    for (int c = 0; c < 32; c++){
        float v = b[c];
        v = fmaf(rx, w[c], v);
        v = fmaf(ry, w[32 + c], v);
        v = fmaf(rz, w[64 + c], v);
        g_A1[c*MK + r] = elu_f(v);
    }
}

// ---------------- deterministic per-channel BN stats -> scale/shift ----------------
__global__ void reduce_bn_kernel(int which, int cols,
                                 const float* __restrict__ g, const float* __restrict__ b,
                                 int off){
    const float* data;
    switch (which){
        case 0: data = g_A1; break;
        case 1: data = g_A2; break;
        case 2: data = g_T0; break;
        case 3: data = g_T1; break;
        default: data = g_T2; break;
    }
    int c = blockIdx.x;
    const float* row = data + (size_t)c*cols;
    float s = 0.f, s2 = 0.f;
    for (int i = threadIdx.x; i < cols; i += blockDim.x){
        float v = row[i];
        s += v;
        s2 = fmaf(v, v, s2);
    }
    __shared__ float ss[256], sq[256];
    ss[threadIdx.x] = s; sq[threadIdx.x] = s2;
    __syncthreads();
    for (int st = 128; st > 0; st >>= 1){
        if (threadIdx.x < st){ ss[threadIdx.x] += ss[threadIdx.x+st]; sq[threadIdx.x] += sq[threadIdx.x+st]; }
        __syncthreads();
    }
    if (threadIdx.x == 0){
        float mean = ss[0] / (float)cols;
        float var  = sq[0] / (float)cols - mean*mean;
        float sc = g[c] * rsqrtf(var + 1e-5f);
        g_stats[off + c] = sc;
        g_stats[off + gridDim.x + c] = b[c] - mean*sc;
    }
}

// ---------------- mlp1 layer 2: 32 -> 32, elu (pre-BN stored) ----------------
__global__ void __launch_bounds__(256) mlp1b_kernel(const float* __restrict__ w1b,
                                                    const float* __restrict__ b1b){
    __shared__ float w[1024];
    int t = threadIdx.x;
    for (int i = t; i < 1024; i += 256) w[i] = w1b[i];
    __syncthreads();
    int r = blockIdx.x*256 + t;
    float hn[32];
    #pragma unroll
    for (int c = 0; c < 32; c++)
        hn[c] = g_A1[c*MK + r]*g_stats[OFF_S1 + c] + g_stats[OFF_S1 + 32 + c];
    #pragma unroll
    for (int co = 0; co < 32; co++){
        float acc = __ldg(&b1b[co]);
        #pragma unroll
        for (int ci = 0; ci < 32; ci++) acc = fmaf(hn[ci], w[ci*32 + co], acc);
        g_A2[co*MK + r] = elu_f(acc);
    }
}

// ---------------- mlp2 dense: rel(48) -> 256, elu (pre-BN stored) ----------------
__global__ void __launch_bounds__(256) mlp2a_kernel(const float* __restrict__ w2,
                                                    const float* __restrict__ b2){
    __shared__ float w[48*256];           // exactly 48KB
    int t = threadIdx.x;
    for (int i = t; i < 48*256; i += 256) w[i] = w2[i];
    __syncthreads();
    int gth = blockIdx.x*256 + t;
    int s = gth >> 13;                    // 0..3: output-channel split
    int m = gth & (MPTS-1);
    float4 pm = g_pos4[m];
    float rel[48];
    #pragma unroll
    for (int k = 0; k < 16; k++){
        int nb = g_idx[m*16 + k];
        float4 pn = g_pos4[nb];
        rel[k*3+0] = pn.x - pm.x;
        rel[k*3+1] = pn.y - pm.y;
        rel[k*3+2] = pn.z - pm.z;
    }
    int o0 = s*64;
    for (int oo = 0; oo < 64; oo++){
        int o = o0 + oo;
        float acc = __ldg(&b2[o]);
        #pragma unroll
        for (int i = 0; i < 48; i++) acc = fmaf(rel[i], w[i*256 + o], acc);
        g_T0[(size_t)o*MPTS + m] = elu_f(acc);
    }
}

// ---------------- grouped conv K->K*K (groups=K): BN(in) -> gconv (+elu) ----------------
template<int STAGE, bool ELU>
__global__ void __launch_bounds__(256) gconv_kernel(const float* __restrict__ wt,
                                                    const float* __restrict__ bias){
    __shared__ float w[4096];
    __shared__ float bs[256];
    int t = threadIdx.x;
    for (int i = t; i < 4096; i += 256) w[i] = wt[i];
    bs[t] = bias[t];
    __syncthreads();
    int m = blockIdx.x*256 + t;
    const float* in  = (STAGE == 0) ? g_T0 : g_T1;
    float*       out = (STAGE == 0) ? g_T1 : g_T2;
    const int    off = (STAGE == 0) ? OFF_SA : OFF_SB;
    for (int cg = 0; cg < 16; cg++){
        float x[16];
        #pragma unroll
        for (int l = 0; l < 16; l++){
            int ch = cg*16 + l;
            x[l] = in[(size_t)ch*MPTS + m]*g_stats[off + ch] + g_stats[off + 256 + ch];
        }
        #pragma unroll
        for (int o = 0; o < 16; o++){
            int ch = cg*16 + o;
            float acc = bs[ch];
            #pragma unroll
            for (int l = 0; l < 16; l++) acc = fmaf(x[l], w[ch*16 + l], acc);
            out[(size_t)ch*MPTS + m] = ELU ? elu_f(acc) : acc;
        }
    }
}

// ---------------- fused per-point: build x_star, apply X-transform, depthwise conv ----------------
__global__ void __launch_bounds__(128) xconv_kernel(const float* __restrict__ xf,
                                                    const float* __restrict__ wcd,
                                                    const float* __restrict__ bcd){
    __shared__ float xs[160*17];
    __shared__ float ts[256];
    __shared__ float xts[160*17];
    __shared__ int   nbr[16];
    int m = blockIdx.x;
    int t = threadIdx.x;
    if (t < 16) nbr[t] = g_idx[m*16 + t];
    #pragma unroll
    for (int e = t; e < 256; e += 128)
        ts[e] = g_T2[(size_t)e*MPTS + m]*g_stats[OFF_SC + e] + g_stats[OFF_SC + 256 + e];
    #pragma unroll
    for (int e = t; e < 512; e += 128){
        int c = e >> 4, k = e & 15;
        xs[c*17 + k] = g_A2[(size_t)c*MK + m*16 + k]*g_stats[OFF_S2 + c] + g_stats[OFF_S2 + 32 + c];
    }
    __syncthreads();
    #pragma unroll
    for (int k = 0; k < 16; k++)
        xs[(32 + t)*17 + k] = __ldg(&xf[(size_t)nbr[k]*CINF + t]);
    __syncthreads();
    // xt[c][j] = sum_k x_star[c][k] * t[k][j]
    #pragma unroll
    for (int i = 0; i < 20; i++){
        int e = t + 128*i;
        int c = e >> 4, j = e & 15;
        float acc = 0.f;
        #pragma unroll
        for (int k = 0; k < 16; k++) acc = fmaf(xs[c*17 + k], ts[k*16 + j], acc);
        xts[c*17 + j] = acc;
    }
    __syncthreads();
    // y[p] (p = c*2+o) = bcd[p] + sum_l xt[c][l]*wcd[c][o][l]
    #pragma unroll
    for (int i = 0; i < 3; i++){
        int p = t + 128*i;
        if (p < 320){
            int c = p >> 1;
            float acc = __ldg(&bcd[p]);
            #pragma unroll
            for (int l = 0; l < 16; l++)
                acc = fmaf(xts[c*17 + l], __ldg(&wcd[p*16 + l]), acc);
            g_Y[(size_t)m*320 + p] = acc;
        }
    }
}

// ---------------- final linear: [8192,320] @ [320,256] + bl ----------------
__global__ void __launch_bounds__(256) gemm_kernel(const float* __restrict__ wl,
                                                   const float* __restrict__ bl,
                                                   float* __restrict__ out){
    __shared__ float As[16*132];
    __shared__ float Bs[16*128];
    int t  = threadIdx.x;
    int bm = blockIdx.x*128, bn = blockIdx.y*128;
    int tx = t & 15, ty = t >> 4;
    float acc[8][8];
    #pragma unroll
    for (int i = 0; i < 8; i++)
        #pragma unroll
        for (int j = 0; j < 8; j++) acc[i][j] = 0.f;

    for (int k0 = 0; k0 < 320; k0 += 16){
        #pragma unroll
        for (int i = 0; i < 2; i++){
            int item = t + 256*i;
            int r = item >> 2, c4 = item & 3;
            float4 v = *(const float4*)&g_Y[(size_t)(bm + r)*320 + k0 + c4*4];
            As[(c4*4+0)*132 + r] = v.x;
            As[(c4*4+1)*132 + r] = v.y;
            As[(c4*4+2)*132 + r] = v.z;
            As[(c4*4+3)*132 + r] = v.w;
        }
        #pragma unroll
        for (int i = 0; i < 2; i++){
            int item = t + 256*i;
            int r = item >> 5, c = (item & 31)*4;
            float4 v = *(const float4*)&wl[(size_t)(k0 + r)*256 + bn + c];
            *(float4*)&Bs[r*128 + c] = v;
        }
        __syncthreads();
        #pragma unroll
        for (int kk = 0; kk < 16; kk++){
            float a[8], b[8];
            #pragma unroll
            for (int i = 0; i < 8; i++) a[i] = As[kk*132 + ty*8 + i];
            #pragma unroll
            for (int j = 0; j < 8; j++) b[j] = Bs[kk*128 + tx*8 + j];
            #pragma unroll
            for (int i = 0; i < 8; i++)
                #pragma unroll
                for (int j = 0; j < 8; j++) acc[i][j] = fmaf(a[i], b[j], acc[i][j]);
        }
        __syncthreads();
    }
    #pragma unroll
    for (int i = 0; i < 8; i++){
        int row = bm + ty*8 + i;
        #pragma unroll
        for (int j = 0; j < 8; j++){
            int col = bn + tx*8 + j;
            out[(size_t)row*256 + col] = acc[i][j] + __ldg(&bl[col]);
        }
    }
}

// ---------------- launch ----------------
extern "C" void kernel_launch(void* const* d_in, const int* in_sizes, int n_in,
                              void* d_out, int out_size){
    const float* x    = (const float*)d_in[0];
    const float* pos  = (const float*)d_in[1];
    const float* w1a  = (const float*)d_in[2];
    const float* b1a  = (const float*)d_in[3];
    const float* g1a  = (const float*)d_in[4];
    const float* be1a = (const float*)d_in[5];
    const float* w1b  = (const float*)d_in[6];
    const float* b1b  = (const float*)d_in[7];
    const float* g1b  = (const float*)d_in[8];
    const float* be1b = (const float*)d_in[9];
    const float* w2   = (const float*)d_in[10];
    const float* b2   = (const float*)d_in[11];
    const float* g2a  = (const float*)d_in[12];
    const float* be2a = (const float*)d_in[13];
    const float* wc2a = (const float*)d_in[14];
    const float* bc2a = (const float*)d_in[15];
    const float* g2b  = (const float*)d_in[16];
    const float* be2b = (const float*)d_in[17];
    const float* wc2b = (const float*)d_in[18];
    const float* bc2b = (const float*)d_in[19];
    const float* g2c  = (const float*)d_in[20];
    const float* be2c = (const float*)d_in[21];
    const float* wcd  = (const float*)d_in[22];
    const float* bcd  = (const float*)d_in[23];
    const float* wl   = (const float*)d_in[24];
    const float* bl   = (const float*)d_in[25];
    float* out = (float*)d_out;

    pack_pos_kernel<<<32, 256>>>(pos);
    knn_kernel<<<256, 128>>>();

    mlp1a_kernel<<<512, 256>>>(w1a, b1a);
    reduce_bn_kernel<<<32, 256>>>(0, MK, g1a, be1a, OFF_S1);
    mlp1b_kernel<<<512, 256>>>(w1b, b1b);
    reduce_bn_kernel<<<32, 256>>>(1, MK, g1b, be1b, OFF_S2);

    mlp2a_kernel<<<128, 256>>>(w2, b2);
    reduce_bn_kernel<<<256, 256>>>(2, MPTS, g2a, be2a, OFF_SA);
    gconv_kernel<0, true><<<32, 256>>>(wc2a, bc2a);
    reduce_bn_kernel<<<256, 256>>>(3, MPTS, g2b, be2b, OFF_SB);
    gconv_kernel<1, false><<<32, 256>>>(wc2b, bc2b);
    reduce_bn_kernel<<<256, 256>>>(4, MPTS, g2c, be2c, OFF_SC);

    xconv_kernel<<<MPTS, 128>>>(x, wcd, bcd);
    gemm_kernel<<<dim3(64, 2), 256>>>(wl, bl, out);
}

// round 4
// speedup vs baseline: 1.4352x; 1.4352x over previous
#include <cuda_runtime.h>
#include <math.h>

#define MPTS 8192
#define KNN  16
#define CINF 128
#define MK   (MPTS*KNN)   // 131072

// ---------------- scratch (device globals; no allocation allowed) ----------------
__device__ float4 g_pos4[MPTS];      // xyz + d2 in .w
__device__ int    g_idx[MK];
__device__ float  g_A1[32*MK];       // mlp1 layer1 (pre-BN), channel-major [32][131072]
__device__ float  g_A2[32*MK];       // mlp1 layer2 (pre-BN)
__device__ float  g_T0[256*MPTS];    // mlp2 dense   (pre-BN), channel-major [256][8192]
__device__ float  g_T1[256*MPTS];    // gconv-a      (pre-BN)
__device__ float  g_T2[256*MPTS];    // gconv-b      (pre-BN)
__device__ float  g_Y[MPTS*320];     // depthwise output, row-major [8192][320]
__device__ float  g_stats[2048];     // BN scale/shift packs
__device__ float  g_psum[2048];      // BN phase-1 partial sums
__device__ float  g_psum2[2048];     // BN phase-1 partial sum-of-squares

#define OFF_S1 0      // 32 scale + 32 shift
#define OFF_S2 64
#define OFF_SA 128    // 256 + 256
#define OFF_SB 640
#define OFF_SC 1152

__device__ __forceinline__ float elu_f(float x){ return x > 0.f ? x : expm1f(x); }

__device__ __forceinline__ const float* bn_src(int which){
    switch (which){
        case 0: return g_A1;
        case 1: return g_A2;
        case 2: return g_T0;
        case 3: return g_T1;
        default: return g_T2;
    }
}

// ---------------- pack pos into float4, with d2 = (x*x + y*y) + z*z in .w ----------------
__global__ void pack_pos_kernel(const float* __restrict__ pos){
    int i = blockIdx.x*blockDim.x + threadIdx.x;
    if (i < MPTS){
        float x = pos[3*i], y = pos[3*i+1], z = pos[3*i+2];
        float d2 = __fadd_rn(__fadd_rn(__fmul_rn(x,x), __fmul_rn(y,y)), __fmul_rn(z,z));
        g_pos4[i] = make_float4(x, y, z, d2);
    }
}

// ---------------- exact kNN replicating reference's Gram-form distance ----------------
__global__ void __launch_bounds__(128) knn_kernel(){
    int lane  = threadIdx.x & 31;
    int split = threadIdx.x >> 5;
    int q = blockIdx.x*32 + lane;
    float4 qp = g_pos4[q];

    float best[16]; int bidx[16];
    #pragma unroll
    for (int s = 0; s < 16; s++){ best[s] = 3.4e38f; bidx[s] = 0x7fffffff; }

    int j0 = split*2048;
    #pragma unroll 4
    for (int j = j0; j < j0 + 2048; j++){
        float4 c = g_pos4[j];
        float dot = __fmaf_rn(qp.z, c.z,
                    __fmaf_rn(qp.y, c.y,
                    __fmul_rn(qp.x, c.x)));
        float d = __fsub_rn(__fadd_rn(qp.w, c.w), __fmul_rn(2.0f, dot));
        if (d < best[15]) {
            float cd = d; int cj = j;
            #pragma unroll
            for (int s = 0; s < 16; s++){
                if (cd < best[s]) {
                    float td = best[s]; best[s] = cd; cd = td;
                    int   ti = bidx[s]; bidx[s] = cj; cj = ti;
                }
            }
        }
    }

    __shared__ float sd[4][32][16];
    __shared__ int   si[4][32][16];
    #pragma unroll
    for (int s = 0; s < 16; s++){ sd[split][lane][s] = best[s]; si[split][lane][s] = bidx[s]; }
    __syncthreads();

    if (split == 0){
        #pragma unroll
        for (int sp = 1; sp < 4; sp++){
            #pragma unroll
            for (int e = 0; e < 16; e++){
                float d = sd[sp][lane][e]; int j = si[sp][lane][e];
                bool ins = (d < best[15]) || (d == best[15] && j < bidx[15]);
                if (ins){
                    float cd = d; int cj = j;
                    #pragma unroll
                    for (int s = 0; s < 16; s++){
                        bool lt = (cd < best[s]) || (cd == best[s] && cj < bidx[s]);
                        if (lt){
                            float td = best[s]; best[s] = cd; cd = td;
                            int   ti = bidx[s]; bidx[s] = cj; cj = ti;
                        }
                    }
                }
            }
        }
        #pragma unroll
        for (int e = 0; e < 16; e++) g_idx[q*16 + e] = bidx[e];
    }
}

// ---------------- mlp1 layer 1: rel(3) -> 32, elu (pre-BN stored) ----------------
__global__ void __launch_bounds__(256) mlp1a_kernel(const float* __restrict__ w1a,
                                                    const float* __restrict__ b1a){
    __shared__ float w[96], b[32];
    int t = threadIdx.x;
    if (t < 96) w[t] = w1a[t];
    if (t < 32) b[t] = b1a[t];
    __syncthreads();
    int r = blockIdx.x*256 + t;          // 0..131071
    int m = r >> 4;
    int nb = g_idx[r];
    float4 pm = g_pos4[m], pn = g_pos4[nb];
    float rx = pn.x - pm.x, ry = pn.y - pm.y, rz = pn.z - pm.z;
    #pragma unroll
    for (int c = 0; c < 32; c++){
        float v = b[c];
        v = fmaf(rx, w[c], v);
        v = fmaf(ry, w[32 + c], v);
        v = fmaf(rz, w[64 + c], v);
        g_A1[c*MK + r] = elu_f(v);
    }
}

// ---------------- BN stats, phase 1: partial sums over chunks (deterministic) ----------------
__global__ void __launch_bounds__(256) bn_phase1_kernel(int which, int cols, int chunks){
    const float* data = bn_src(which);
    int c = blockIdx.x / chunks;
    int k = blockIdx.x - c*chunks;
    int seg = cols / chunks;
    const float* row = data + (size_t)c*cols + (size_t)k*seg;
    float s = 0.f, s2 = 0.f;
    for (int i = threadIdx.x*4; i < seg; i += 256*4){
        float4 v = *(const float4*)(row + i);
        s = ((s + v.x) + v.y) + (v.z + v.w);
        s2 = fmaf(v.w, v.w, fmaf(v.z, v.z, fmaf(v.y, v.y, fmaf(v.x, v.x, s2))));
    }
    // warp reduce (fixed xor order -> deterministic)
    #pragma unroll
    for (int o = 16; o > 0; o >>= 1){
        s  += __shfl_xor_sync(0xffffffff, s,  o);
        s2 += __shfl_xor_sync(0xffffffff, s2, o);
    }
    __shared__ float ws[8], ws2[8];
    int wid = threadIdx.x >> 5;
    if ((threadIdx.x & 31) == 0){ ws[wid] = s; ws2[wid] = s2; }
    __syncthreads();
    if (threadIdx.x == 0){
        float ts = ws[0], ts2 = ws2[0];
        #pragma unroll
        for (int w2 = 1; w2 < 8; w2++){ ts += ws[w2]; ts2 += ws2[w2]; }
        g_psum[blockIdx.x]  = ts;
        g_psum2[blockIdx.x] = ts2;
    }
}

// ---------------- BN stats, phase 2: fold partials -> scale/shift ----------------
__global__ void __launch_bounds__(32) bn_phase2_kernel(int chunks, int channels, int cols,
                                                       const float* __restrict__ g,
                                                       const float* __restrict__ b,
                                                       int off){
    int c = blockIdx.x;
    float s = 0.f, s2 = 0.f;
    for (int i = threadIdx.x; i < chunks; i += 32){
        s  += g_psum[c*chunks + i];
        s2 += g_psum2[c*chunks + i];
    }
    #pragma unroll
    for (int o = 16; o > 0; o >>= 1){
        s  += __shfl_xor_sync(0xffffffff, s,  o);
        s2 += __shfl_xor_sync(0xffffffff, s2, o);
    }
    if (threadIdx.x == 0){
        float mean = s / (float)cols;
        float var  = s2 / (float)cols - mean*mean;
        float sc = g[c] * rsqrtf(var + 1e-5f);
        g_stats[off + c] = sc;
        g_stats[off + channels + c] = b[c] - mean*sc;
    }
}

// ---------------- mlp1 layer 2: 32 -> 32, elu (pre-BN stored) ----------------
__global__ void __launch_bounds__(256) mlp1b_kernel(const float* __restrict__ w1b,
                                                    const float* __restrict__ b1b){
    __shared__ float w[1024];
    int t = threadIdx.x;
    for (int i = t; i < 1024; i += 256) w[i] = w1b[i];
    __syncthreads();
    int r = blockIdx.x*256 + t;
    float hn[32];
    #pragma unroll
    for (int c = 0; c < 32; c++)
        hn[c] = g_A1[c*MK + r]*g_stats[OFF_S1 + c] + g_stats[OFF_S1 + 32 + c];
    #pragma unroll
    for (int co = 0; co < 32; co++){
        float acc = __ldg(&b1b[co]);
        #pragma unroll
        for (int ci = 0; ci < 32; ci++) acc = fmaf(hn[ci], w[ci*32 + co], acc);
        g_A2[co*MK + r] = elu_f(acc);
    }
}

// ---------------- mlp2 dense: rel(48) -> 256, elu (pre-BN stored) ----------------
__global__ void __launch_bounds__(256) mlp2a_kernel(const float* __restrict__ w2,
                                                    const float* __restrict__ b2){
    __shared__ float w[48*256];           // exactly 48KB
    int t = threadIdx.x;
    for (int i = t; i < 48*256; i += 256) w[i] = w2[i];
    __syncthreads();
    int gth = blockIdx.x*256 + t;
    int s = gth >> 13;                    // 0..3: output-channel split
    int m = gth & (MPTS-1);
    float4 pm = g_pos4[m];
    float rel[48];
    #pragma unroll
    for (int k = 0; k < 16; k++){
        int nb = g_idx[m*16 + k];
        float4 pn = g_pos4[nb];
        rel[k*3+0] = pn.x - pm.x;
        rel[k*3+1] = pn.y - pm.y;
        rel[k*3+2] = pn.z - pm.z;
    }
    int o0 = s*64;
    for (int oo = 0; oo < 64; oo++){
        int o = o0 + oo;
        float acc = __ldg(&b2[o]);
        #pragma unroll
        for (int i = 0; i < 48; i++) acc = fmaf(rel[i], w[i*256 + o], acc);
        g_T0[(size_t)o*MPTS + m] = elu_f(acc);
    }
}

// ---------------- grouped conv K->K*K (groups=K): one (point, group) per thread ----------------
template<int STAGE, bool ELU>
__global__ void __launch_bounds__(256) gconv_kernel(const float* __restrict__ wt,
                                                    const float* __restrict__ bias){
    int e  = blockIdx.x*256 + threadIdx.x;   // grid 512 -> 131072 = 8192 pts x 16 groups
    int m  = e & (MPTS-1);
    int cg = e >> 13;
    __shared__ float w[256];                 // this block's group weights
    __shared__ float bs[16];
    if (threadIdx.x < 16) bs[threadIdx.x] = bias[cg*16 + threadIdx.x];
    w[threadIdx.x] = wt[cg*256 + threadIdx.x];
    __syncthreads();

    const float* in  = (STAGE == 0) ? g_T0 : g_T1;
    float*       out = (STAGE == 0) ? g_T1 : g_T2;
    const int    off = (STAGE == 0) ? OFF_SA : OFF_SB;

    float x[16];
    #pragma unroll
    for (int l = 0; l < 16; l++){
        int ch = cg*16 + l;
        x[l] = in[(size_t)ch*MPTS + m]*g_stats[off + ch] + g_stats[off + 256 + ch];
    }
    #pragma unroll
    for (int o = 0; o < 16; o++){
        float acc = bs[o];
        #pragma unroll
        for (int l = 0; l < 16; l++) acc = fmaf(x[l], w[o*16 + l], acc);
        out[(size_t)(cg*16 + o)*MPTS + m] = ELU ? elu_f(acc) : acc;
    }
}

// ---------------- fused per-point: build x_star, apply X-transform, depthwise conv ----------------
__global__ void __launch_bounds__(128) xconv_kernel(const float* __restrict__ xf,
                                                    const float* __restrict__ wcd,
                                                    const float* __restrict__ bcd){
    __shared__ float xs[160*17];
    __shared__ float ts[256];
    __shared__ float xts[160*17];
    __shared__ int   nbr[16];
    int m = blockIdx.x;
    int t = threadIdx.x;
    if (t < 16) nbr[t] = g_idx[m*16 + t];
    #pragma unroll
    for (int e = t; e < 256; e += 128)
        ts[e] = g_T2[(size_t)e*MPTS + m]*g_stats[OFF_SC + e] + g_stats[OFF_SC + 256 + e];
    #pragma unroll
    for (int e = t; e < 512; e += 128){
        int c = e >> 4, k = e & 15;
        xs[c*17 + k] = g_A2[(size_t)c*MK + m*16 + k]*g_stats[OFF_S2 + c] + g_stats[OFF_S2 + 32 + c];
    }
    __syncthreads();
    #pragma unroll
    for (int k = 0; k < 16; k++)
        xs[(32 + t)*17 + k] = __ldg(&xf[(size_t)nbr[k]*CINF + t]);
    __syncthreads();
    // xt[c][j] = sum_k x_star[c][k] * t[k][j]
    #pragma unroll
    for (int i = 0; i < 20; i++){
        int e = t + 128*i;
        int c = e >> 4, j = e & 15;
        float acc = 0.f;
        #pragma unroll
        for (int k = 0; k < 16; k++) acc = fmaf(xs[c*17 + k], ts[k*16 + j], acc);
        xts[c*17 + j] = acc;
    }
    __syncthreads();
    // y[p] (p = c*2+o) = bcd[p] + sum_l xt[c][l]*wcd[c][o][l]
    #pragma unroll
    for (int i = 0; i < 3; i++){
        int p = t + 128*i;
        if (p < 320){
            int c = p >> 1;
            float acc = __ldg(&bcd[p]);
            #pragma unroll
            for (int l = 0; l < 16; l++)
                acc = fmaf(xts[c*17 + l], __ldg(&wcd[p*16 + l]), acc);
            g_Y[(size_t)m*320 + p] = acc;
        }
    }
}

// ---------------- final linear: [8192,320] @ [320,256] + bl ----------------
__global__ void __launch_bounds__(256) gemm_kernel(const float* __restrict__ wl,
                                                   const float* __restrict__ bl,
                                                   float* __restrict__ out){
    __shared__ float As[16*132];
    __shared__ float Bs[16*128];
    int t  = threadIdx.x;
    int bm = blockIdx.x*128, bn = blockIdx.y*128;
    int tx = t & 15, ty = t >> 4;
    float acc[8][8];
    #pragma unroll
    for (int i = 0; i < 8; i++)
        #pragma unroll
        for (int j = 0; j < 8; j++) acc[i][j] = 0.f;

    for (int k0 = 0; k0 < 320; k0 += 16){
        #pragma unroll
        for (int i = 0; i < 2; i++){
            int item = t + 256*i;
            int r = item >> 2, c4 = item & 3;
            float4 v = *(const float4*)&g_Y[(size_t)(bm + r)*320 + k0 + c4*4];
            As[(c4*4+0)*132 + r] = v.x;
            As[(c4*4+1)*132 + r] = v.y;
            As[(c4*4+2)*132 + r] = v.z;
            As[(c4*4+3)*132 + r] = v.w;
        }
        #pragma unroll
        for (int i = 0; i < 2; i++){
            int item = t + 256*i;
            int r = item >> 5, c = (item & 31)*4;
            float4 v = *(const float4*)&wl[(size_t)(k0 + r)*256 + bn + c];
            *(float4*)&Bs[r*128 + c] = v;
        }
        __syncthreads();
        #pragma unroll
        for (int kk = 0; kk < 16; kk++){
            float a[8], b[8];
            #pragma unroll
            for (int i = 0; i < 8; i++) a[i] = As[kk*132 + ty*8 + i];
            #pragma unroll
            for (int j = 0; j < 8; j++) b[j] = Bs[kk*128 + tx*8 + j];
            #pragma unroll
            for (int i = 0; i < 8; i++)
                #pragma unroll
                for (int j = 0; j < 8; j++) acc[i][j] = fmaf(a[i], b[j], acc[i][j]);
        }
        __syncthreads();
    }
    #pragma unroll
    for (int i = 0; i < 8; i++){
        int row = bm + ty*8 + i;
        #pragma unroll
        for (int j = 0; j < 8; j++){
            int col = bn + tx*8 + j;
            out[(size_t)row*256 + col] = acc[i][j] + __ldg(&bl[col]);
        }
    }
}

// ---------------- launch ----------------
extern "C" void kernel_launch(void* const* d_in, const int* in_sizes, int n_in,
                              void* d_out, int out_size){
    const float* x    = (const float*)d_in[0];
    const float* pos  = (const float*)d_in[1];
    const float* w1a  = (const float*)d_in[2];
    const float* b1a  = (const float*)d_in[3];
    const float* g1a  = (const float*)d_in[4];
    const float* be1a = (const float*)d_in[5];
    const float* w1b  = (const float*)d_in[6];
    const float* b1b  = (const float*)d_in[7];
    const float* g1b  = (const float*)d_in[8];
    const float* be1b = (const float*)d_in[9];
    const float* w2   = (const float*)d_in[10];
    const float* b2   = (const float*)d_in[11];
    const float* g2a  = (const float*)d_in[12];
    const float* be2a = (const float*)d_in[13];
    const float* wc2a = (const float*)d_in[14];
    const float* bc2a = (const float*)d_in[15];
    const float* g2b  = (const float*)d_in[16];
    const float* be2b = (const float*)d_in[17];
    const float* wc2b = (const float*)d_in[18];
    const float* bc2b = (const float*)d_in[19];
    const float* g2c  = (const float*)d_in[20];
    const float* be2c = (const float*)d_in[21];
    const float* wcd  = (const float*)d_in[22];
    const float* bcd  = (const float*)d_in[23];
    const float* wl   = (const float*)d_in[24];
    const float* bl   = (const float*)d_in[25];
    float* out = (float*)d_out;

    pack_pos_kernel<<<32, 256>>>(pos);
    knn_kernel<<<256, 128>>>();

    mlp1a_kernel<<<512, 256>>>(w1a, b1a);
    bn_phase1_kernel<<<2048, 256>>>(0, MK, 64);
    bn_phase2_kernel<<<32, 32>>>(64, 32, MK, g1a, be1a, OFF_S1);
    mlp1b_kernel<<<512, 256>>>(w1b, b1b);
    bn_phase1_kernel<<<2048, 256>>>(1, MK, 64);
    bn_phase2_kernel<<<32, 32>>>(64, 32, MK, g1b, be1b, OFF_S2);

    mlp2a_kernel<<<128, 256>>>(w2, b2);
    bn_phase1_kernel<<<2048, 256>>>(2, MPTS, 8);
    bn_phase2_kernel<<<256, 32>>>(8, 256, MPTS, g2a, be2a, OFF_SA);
    gconv_kernel<0, true><<<512, 256>>>(wc2a, bc2a);
    bn_phase1_kernel<<<2048, 256>>>(3, MPTS, 8);
    bn_phase2_kernel<<<256, 32>>>(8, 256, MPTS, g2b, be2b, OFF_SB);
    gconv_kernel<1, false><<<512, 256>>>(wc2b, bc2b);
    bn_phase1_kernel<<<2048, 256>>>(4, MPTS, 8);
    bn_phase2_kernel<<<256, 32>>>(8, 256, MPTS, g2c, be2c, OFF_SC);

    xconv_kernel<<<MPTS, 128>>>(x, wcd, bcd);
    gemm_kernel<<<dim3(64, 2), 256>>>(wl, bl, out);
}

// round 5
// speedup vs baseline: 1.4432x; 1.0055x over previous
#include <cuda_runtime.h>
#include <math.h>

#define MPTS 8192
#define KNN  16
#define CINF 128
#define MK   (MPTS*KNN)   // 131072

// ---------------- scratch (device globals; no allocation allowed) ----------------
__device__ float4 g_pos4[MPTS];      // xyz + d2 in .w
__device__ int    g_idx[MK];
__device__ float  g_A1[32*MK];       // mlp1 layer1 (pre-BN), channel-major [32][131072]
__device__ float  g_A2[32*MK];       // mlp1 layer2 (pre-BN)
__device__ float  g_T0[256*MPTS];    // mlp2 dense   (pre-BN), channel-major [256][8192]
__device__ float  g_T1[256*MPTS];    // gconv-a      (pre-BN)
__device__ float  g_T2[256*MPTS];    // gconv-b      (pre-BN)
__device__ float  g_Y[MPTS*320];     // depthwise output, row-major [8192][320]
__device__ float  g_stats[2048];     // BN scale/shift packs
__device__ float  g_psum[16384];     // BN partial sums   [ch*chunks + chunk]
__device__ float  g_psum2[16384];    // BN partial sumsq

#define OFF_S1 0      // 32 scale + 32 shift
#define OFF_S2 64
#define OFF_SA 128    // 256 + 256
#define OFF_SB 640
#define OFF_SC 1152

__device__ __forceinline__ float elu_f(float x){ return x > 0.f ? x : expm1f(x); }

__device__ __forceinline__ void warp_red2(float& s, float& q){
    #pragma unroll
    for (int o = 16; o > 0; o >>= 1){
        s += __shfl_xor_sync(0xffffffff, s, o);
        q += __shfl_xor_sync(0xffffffff, q, o);
    }
}

// ---------------- pack pos into float4, with d2 = (x*x + y*y) + z*z in .w ----------------
__global__ void pack_pos_kernel(const float* __restrict__ pos){
    int i = blockIdx.x*blockDim.x + threadIdx.x;
    if (i < MPTS){
        float x = pos[3*i], y = pos[3*i+1], z = pos[3*i+2];
        float d2 = __fadd_rn(__fadd_rn(__fmul_rn(x,x), __fmul_rn(y,y)), __fmul_rn(z,z));
        g_pos4[i] = make_float4(x, y, z, d2);
    }
}

// ---------------- exact kNN replicating reference's Gram-form distance ----------------
__global__ void __launch_bounds__(128) knn_kernel(){
    int lane  = threadIdx.x & 31;
    int split = threadIdx.x >> 5;
    int q = blockIdx.x*32 + lane;
    float4 qp = g_pos4[q];

    float best[16]; int bidx[16];
    #pragma unroll
    for (int s = 0; s < 16; s++){ best[s] = 3.4e38f; bidx[s] = 0x7fffffff; }

    int j0 = split*2048;
    #pragma unroll 4
    for (int j = j0; j < j0 + 2048; j++){
        float4 c = g_pos4[j];
        float dot = __fmaf_rn(qp.z, c.z,
                    __fmaf_rn(qp.y, c.y,
                    __fmul_rn(qp.x, c.x)));
        float d = __fsub_rn(__fadd_rn(qp.w, c.w), __fmul_rn(2.0f, dot));
        if (d < best[15]) {
            float cd = d; int cj = j;
            #pragma unroll
            for (int s = 0; s < 16; s++){
                if (cd < best[s]) {
                    float td = best[s]; best[s] = cd; cd = td;
                    int   ti = bidx[s]; bidx[s] = cj; cj = ti;
                }
            }
        }
    }

    __shared__ float sd[4][32][16];
    __shared__ int   si[4][32][16];
    #pragma unroll
    for (int s = 0; s < 16; s++){ sd[split][lane][s] = best[s]; si[split][lane][s] = bidx[s]; }
    __syncthreads();

    if (split == 0){
        #pragma unroll
        for (int sp = 1; sp < 4; sp++){
            #pragma unroll
            for (int e = 0; e < 16; e++){
                float d = sd[sp][lane][e]; int j = si[sp][lane][e];
                bool ins = (d < best[15]) || (d == best[15] && j < bidx[15]);
                if (ins){
                    float cd = d; int cj = j;
                    #pragma unroll
                    for (int s = 0; s < 16; s++){
                        bool lt = (cd < best[s]) || (cd == best[s] && cj < bidx[s]);
                        if (lt){
                            float td = best[s]; best[s] = cd; cd = td;
                            int   ti = bidx[s]; bidx[s] = cj; cj = ti;
                        }
                    }
                }
            }
        }
        #pragma unroll
        for (int e = 0; e < 16; e++) g_idx[q*16 + e] = bidx[e];
    }
}

// ---------------- mlp1 layer 1: rel(3) -> 32, elu + fused BN partials ----------------
__global__ void __launch_bounds__(256) mlp1a_kernel(const float* __restrict__ w1a,
                                                    const float* __restrict__ b1a){
    __shared__ float w[96], b[32];
    __shared__ float ws[32][8], wq[32][8];
    int t = threadIdx.x;
    int lane = t & 31, wid = t >> 5;
    if (t < 96) w[t] = w1a[t];
    if (t < 32) b[t] = b1a[t];
    __syncthreads();
    int r = blockIdx.x*256 + t;          // 0..131071
    int m = r >> 4;
    int nb = g_idx[r];
    float4 pm = g_pos4[m], pn = g_pos4[nb];
    float rx = pn.x - pm.x, ry = pn.y - pm.y, rz = pn.z - pm.z;
    #pragma unroll
    for (int c = 0; c < 32; c++){
        float v = b[c];
        v = fmaf(rx, w[c], v);
        v = fmaf(ry, w[32 + c], v);
        v = fmaf(rz, w[64 + c], v);
        v = elu_f(v);
        g_A1[c*MK + r] = v;
        float s = v, q2 = v*v;
        warp_red2(s, q2);
        if (lane == 0){ ws[c][wid] = s; wq[c][wid] = q2; }
    }
    __syncthreads();
    if (t < 32){
        float s = ws[t][0], q2 = wq[t][0];
        #pragma unroll
        for (int k = 1; k < 8; k++){ s += ws[t][k]; q2 += wq[t][k]; }
        g_psum[t*512 + blockIdx.x]  = s;
        g_psum2[t*512 + blockIdx.x] = q2;
    }
}

// ---------------- BN phase 2: fold partials -> scale/shift ----------------
__global__ void __launch_bounds__(32) bn_phase2_kernel(int chunks, int channels, int cols,
                                                       const float* __restrict__ g,
                                                       const float* __restrict__ b,
                                                       int off){
    int c = blockIdx.x;
    float s = 0.f, s2 = 0.f;
    for (int i = threadIdx.x; i < chunks; i += 32){
        s  += g_psum[c*chunks + i];
        s2 += g_psum2[c*chunks + i];
    }
    warp_red2(s, s2);
    if (threadIdx.x == 0){
        float mean = s / (float)cols;
        float var  = s2 / (float)cols - mean*mean;
        float sc = g[c] * rsqrtf(var + 1e-5f);
        g_stats[off + c] = sc;
        g_stats[off + channels + c] = b[c] - mean*sc;
    }
}

// ---------------- mlp1 layer 2: 32 -> 32, elu + fused BN partials ----------------
__global__ void __launch_bounds__(256) mlp1b_kernel(const float* __restrict__ w1b,
                                                    const float* __restrict__ b1b){
    __shared__ float w[1024];
    __shared__ float ws[32][8], wq[32][8];
    int t = threadIdx.x;
    int lane = t & 31, wid = t >> 5;
    for (int i = t; i < 1024; i += 256) w[i] = w1b[i];
    __syncthreads();
    int r = blockIdx.x*256 + t;
    float hn[32];
    #pragma unroll
    for (int c = 0; c < 32; c++)
        hn[c] = g_A1[c*MK + r]*g_stats[OFF_S1 + c] + g_stats[OFF_S1 + 32 + c];
    #pragma unroll
    for (int co = 0; co < 32; co++){
        float acc = __ldg(&b1b[co]);
        #pragma unroll
        for (int ci = 0; ci < 32; ci++) acc = fmaf(hn[ci], w[ci*32 + co], acc);
        acc = elu_f(acc);
        g_A2[co*MK + r] = acc;
        float s = acc, q2 = acc*acc;
        warp_red2(s, q2);
        if (lane == 0){ ws[co][wid] = s; wq[co][wid] = q2; }
    }
    __syncthreads();
    if (t < 32){
        float s = ws[t][0], q2 = wq[t][0];
        #pragma unroll
        for (int k = 1; k < 8; k++){ s += ws[t][k]; q2 += wq[t][k]; }
        g_psum[t*512 + blockIdx.x]  = s;
        g_psum2[t*512 + blockIdx.x] = q2;
    }
}

// ---------------- mlp2 dense: rel(48) -> 256, elu + fused BN partials ----------------
__global__ void __launch_bounds__(256) mlp2a_kernel(const float* __restrict__ w2,
                                                    const float* __restrict__ b2){
    __shared__ float w[48*256];           // 48KB
    __shared__ float ws[64][8], wq[64][8];
    int t = threadIdx.x;
    int lane = t & 31, wid = t >> 5;
    for (int i = t; i < 48*256; i += 256) w[i] = w2[i];
    __syncthreads();
    int gth = blockIdx.x*256 + t;
    int s = blockIdx.x >> 5;              // output-channel split 0..3 (constant per block)
    int m = gth & (MPTS-1);
    int chunk = blockIdx.x & 31;
    float4 pm = g_pos4[m];
    float rel[48];
    #pragma unroll
    for (int k = 0; k < 16; k++){
        int nb = g_idx[m*16 + k];
        float4 pn = g_pos4[nb];
        rel[k*3+0] = pn.x - pm.x;
        rel[k*3+1] = pn.y - pm.y;
        rel[k*3+2] = pn.z - pm.z;
    }
    int o0 = s*64;
    for (int oo = 0; oo < 64; oo++){
        int o = o0 + oo;
        float acc = __ldg(&b2[o]);
        #pragma unroll
        for (int i = 0; i < 48; i++) acc = fmaf(rel[i], w[i*256 + o], acc);
        acc = elu_f(acc);
        g_T0[(size_t)o*MPTS + m] = acc;
        float sv = acc, q2 = acc*acc;
        warp_red2(sv, q2);
        if (lane == 0){ ws[oo][wid] = sv; wq[oo][wid] = q2; }
    }
    __syncthreads();
    if (t < 64){
        float sv = ws[t][0], q2 = wq[t][0];
        #pragma unroll
        for (int k = 1; k < 8; k++){ sv += ws[t][k]; q2 += wq[t][k]; }
        g_psum[(o0 + t)*32 + chunk]  = sv;
        g_psum2[(o0 + t)*32 + chunk] = q2;
    }
}

// ---------------- grouped conv K->K*K: BN(in) -> gconv (+elu) + fused BN partials ----------------
template<int STAGE, bool ELU>
__global__ void __launch_bounds__(256) gconv_kernel(const float* __restrict__ wt,
                                                    const float* __restrict__ bias){
    int e  = blockIdx.x*256 + threadIdx.x;   // 131072 = 8192 pts x 16 groups
    int m  = e & (MPTS-1);
    int cg = blockIdx.x >> 5;                // group, constant per block
    int chunk = blockIdx.x & 31;
    __shared__ float w[256];
    __shared__ float bs[16];
    __shared__ float ws[16][8], wq[16][8];
    int t = threadIdx.x;
    int lane = t & 31, wid = t >> 5;
    if (t < 16) bs[t] = bias[cg*16 + t];
    w[t] = wt[cg*256 + t];
    __syncthreads();

    const float* in  = (STAGE == 0) ? g_T0 : g_T1;
    float*       out = (STAGE == 0) ? g_T1 : g_T2;
    const int    off = (STAGE == 0) ? OFF_SA : OFF_SB;

    float x[16];
    #pragma unroll
    for (int l = 0; l < 16; l++){
        int ch = cg*16 + l;
        x[l] = in[(size_t)ch*MPTS + m]*g_stats[off + ch] + g_stats[off + 256 + ch];
    }
    #pragma unroll
    for (int o = 0; o < 16; o++){
        float acc = bs[o];
        #pragma unroll
        for (int l = 0; l < 16; l++) acc = fmaf(x[l], w[o*16 + l], acc);
        if (ELU) acc = elu_f(acc);
        out[(size_t)(cg*16 + o)*MPTS + m] = acc;
        float sv = acc, q2 = acc*acc;
        warp_red2(sv, q2);
        if (lane == 0){ ws[o][wid] = sv; wq[o][wid] = q2; }
    }
    __syncthreads();
    if (t < 16){
        float sv = ws[t][0], q2 = wq[t][0];
        #pragma unroll
        for (int k = 1; k < 8; k++){ sv += ws[t][k]; q2 += wq[t][k]; }
        g_psum[(cg*16 + t)*32 + chunk]  = sv;
        g_psum2[(cg*16 + t)*32 + chunk] = q2;
    }
}

// ---------------- fused per-point: build x_star, apply X-transform, depthwise conv ----------------
__global__ void __launch_bounds__(128) xconv_kernel(const float* __restrict__ xf,
                                                    const float* __restrict__ wcd,
                                                    const float* __restrict__ bcd){
    __shared__ float xs[160*17];
    __shared__ float ts[256];
    __shared__ float xts[160*17];
    __shared__ int   nbr[16];
    int m = blockIdx.x;
    int t = threadIdx.x;
    if (t < 16) nbr[t] = g_idx[m*16 + t];
    #pragma unroll
    for (int e = t; e < 256; e += 128)
        ts[e] = g_T2[(size_t)e*MPTS + m]*g_stats[OFF_SC + e] + g_stats[OFF_SC + 256 + e];
    #pragma unroll
    for (int e = t; e < 512; e += 128){
        int c = e >> 4, k = e & 15;
        xs[c*17 + k] = g_A2[(size_t)c*MK + m*16 + k]*g_stats[OFF_S2 + c] + g_stats[OFF_S2 + 32 + c];
    }
    __syncthreads();
    #pragma unroll
    for (int k = 0; k < 16; k++)
        xs[(32 + t)*17 + k] = __ldg(&xf[(size_t)nbr[k]*CINF + t]);
    __syncthreads();
    // xt[c][j] = sum_k x_star[c][k] * t[k][j]; fixed j per thread -> ts cached in regs
    int j = t & 15, c0 = t >> 4;
    float tr[16];
    #pragma unroll
    for (int k = 0; k < 16; k++) tr[k] = ts[k*16 + j];
    #pragma unroll
    for (int i = 0; i < 20; i++){
        int c = c0 + 8*i;
        float acc = 0.f;
        #pragma unroll
        for (int k = 0; k < 16; k++) acc = fmaf(xs[c*17 + k], tr[k], acc);
        xts[c*17 + j] = acc;
    }
    __syncthreads();
    // y[p] (p = c*2+o) = bcd[p] + sum_l xt[c][l]*wcd[c][o][l]
    #pragma unroll
    for (int i = 0; i < 3; i++){
        int p = t + 128*i;
        if (p < 320){
            int c = p >> 1;
            float acc = __ldg(&bcd[p]);
            #pragma unroll
            for (int l = 0; l < 16; l++)
                acc = fmaf(xts[c*17 + l], __ldg(&wcd[p*16 + l]), acc);
            g_Y[(size_t)m*320 + p] = acc;
        }
    }
}

// ---------------- final linear: [8192,320] @ [320,256] + bl ----------------
__global__ void __launch_bounds__(256) gemm_kernel(const float* __restrict__ wl,
                                                   const float* __restrict__ bl,
                                                   float* __restrict__ out){
    __shared__ float As[16*132];
    __shared__ float Bs[16*128];
    int t  = threadIdx.x;
    int bm = blockIdx.x*128, bn = blockIdx.y*128;
    int tx = t & 15, ty = t >> 4;
    float acc[8][8];
    #pragma unroll
    for (int i = 0; i < 8; i++)
        #pragma unroll
        for (int j = 0; j < 8; j++) acc[i][j] = 0.f;

    for (int k0 = 0; k0 < 320; k0 += 16){
        #pragma unroll
        for (int i = 0; i < 2; i++){
            int item = t + 256*i;
            int r = item >> 2, c4 = item & 3;
            float4 v = *(const float4*)&g_Y[(size_t)(bm + r)*320 + k0 + c4*4];
            As[(c4*4+0)*132 + r] = v.x;
            As[(c4*4+1)*132 + r] = v.y;
            As[(c4*4+2)*132 + r] = v.z;
            As[(c4*4+3)*132 + r] = v.w;
        }
        #pragma unroll
        for (int i = 0; i < 2; i++){
            int item = t + 256*i;
            int r = item >> 5, c = (item & 31)*4;
            float4 v = *(const float4*)&wl[(size_t)(k0 + r)*256 + bn + c];
            *(float4*)&Bs[r*128 + c] = v;
        }
        __syncthreads();
        #pragma unroll
        for (int kk = 0; kk < 16; kk++){
            float a[8], b[8];
            #pragma unroll
            for (int i = 0; i < 8; i++) a[i] = As[kk*132 + ty*8 + i];
            #pragma unroll
            for (int j = 0; j < 8; j++) b[j] = Bs[kk*128 + tx*8 + j];
            #pragma unroll
            for (int i = 0; i < 8; i++)
                #pragma unroll
                for (int j = 0; j < 8; j++) acc[i][j] = fmaf(a[i], b[j], acc[i][j]);
        }
        __syncthreads();
    }
    #pragma unroll
    for (int i = 0; i < 8; i++){
        int row = bm + ty*8 + i;
        #pragma unroll
        for (int j = 0; j < 8; j++){
            int col = bn + tx*8 + j;
            out[(size_t)row*256 + col] = acc[i][j] + __ldg(&bl[col]);
        }
    }
}

// ---------------- launch ----------------
extern "C" void kernel_launch(void* const* d_in, const int* in_sizes, int n_in,
                              void* d_out, int out_size){
    const float* x    = (const float*)d_in[0];
    const float* pos  = (const float*)d_in[1];
    const float* w1a  = (const float*)d_in[2];
    const float* b1a  = (const float*)d_in[3];
    const float* g1a  = (const float*)d_in[4];
    const float* be1a = (const float*)d_in[5];
    const float* w1b  = (const float*)d_in[6];
    const float* b1b  = (const float*)d_in[7];
    const float* g1b  = (const float*)d_in[8];
    const float* be1b = (const float*)d_in[9];
    const float* w2   = (const float*)d_in[10];
    const float* b2   = (const float*)d_in[11];
    const float* g2a  = (const float*)d_in[12];
    const float* be2a = (const float*)d_in[13];
    const float* wc2a = (const float*)d_in[14];
    const float* bc2a = (const float*)d_in[15];
    const float* g2b  = (const float*)d_in[16];
    const float* be2b = (const float*)d_in[17];
    const float* wc2b = (const float*)d_in[18];
    const float* bc2b = (const float*)d_in[19];
    const float* g2c  = (const float*)d_in[20];
    const float* be2c = (const float*)d_in[21];
    const float* wcd  = (const float*)d_in[22];
    const float* bcd  = (const float*)d_in[23];
    const float* wl   = (const float*)d_in[24];
    const float* bl   = (const float*)d_in[25];
    float* out = (float*)d_out;

    pack_pos_kernel<<<32, 256>>>(pos);
    knn_kernel<<<256, 128>>>();

    mlp1a_kernel<<<512, 256>>>(w1a, b1a);
    bn_phase2_kernel<<<32, 32>>>(512, 32, MK, g1a, be1a, OFF_S1);
    mlp1b_kernel<<<512, 256>>>(w1b, b1b);
    bn_phase2_kernel<<<32, 32>>>(512, 32, MK, g1b, be1b, OFF_S2);

    mlp2a_kernel<<<128, 256>>>(w2, b2);
    bn_phase2_kernel<<<256, 32>>>(32, 256, MPTS, g2a, be2a, OFF_SA);
    gconv_kernel<0, true><<<512, 256>>>(wc2a, bc2a);
    bn_phase2_kernel<<<256, 32>>>(32, 256, MPTS, g2b, be2b, OFF_SB);
    gconv_kernel<1, false><<<512, 256>>>(wc2b, bc2b);
    bn_phase2_kernel<<<256, 32>>>(32, 256, MPTS, g2c, be2c, OFF_SC);

    xconv_kernel<<<MPTS, 128>>>(x, wcd, bcd);
    gemm_kernel<<<dim3(64, 2), 256>>>(wl, bl, out);
}